// round 16
// baseline (speedup 1.0000x reference)
#include <cuda_runtime.h>
#include <stdint.h>

#define NB 32
#define NC 512
#define T_IN 1024
#define T_OUT 4096

#define CPB 8                    // channels per CTA -> grid = 2048
#define NT  256                  // threads per CTA
#define EPT (T_IN / NT)          // durations per thread in the scan = 4
#define NW  (NT / 32)            // warps per CTA = 8

// ---------------------------------------------------------------------------
// Fused kernel (R15 + deeper MLP). CTA = (batch, 8 channels).
//   Phase A: scan durations, scatter run-length index map into smem (int32).
//   Phase B: gather 2 channels x 2 t-groups per step: 16 independent LDGs
//            in flight before the 4 streaming STG.128s. In-flight model from
//            R12/R15: DRAM% tracks (resident warps x loads-in-flight); this
//            config gives 3 CTA/SM x 8 warps x 16 = 384 vs R15's 320.
// __launch_bounds__(256,3): 85-reg ceiling, comfortably above the ~82 natural
// usage -> no spills (the R13 hard-cap mistake).
// Durations int32-vs-int64 detected on-device (odd words all zero => int64).
// ---------------------------------------------------------------------------
__global__ __launch_bounds__(NT, 3)
void length_regulate_kernel(const float* __restrict__ enc,
                            const int*   __restrict__ dur32,
                            float*       __restrict__ out) {
    const int groups_per_b = NC / CPB;              // 64
    const int b  = blockIdx.x / groups_per_b;
    const int cg = blockIdx.x % groups_per_b;
    const int tid = threadIdx.x;

    __shared__ int sidx[T_OUT];                     // 16 KB index map
    __shared__ int wsum[NW];

    // ---- dtype detection: OR of odd words in first 2048 int32s ----
    int odd = 0;
#pragma unroll
    for (int i = 0; i < T_IN / NT; ++i)
        odd |= dur32[2 * (i * NT + tid) + 1];
    const bool is32 = __syncthreads_or(odd) != 0;

    // ---- Phase A: scan + scatter (proven logic) ----
    int d[EPT];
    {
        const int j0 = tid * EPT;
        if (is32) {
#pragma unroll
            for (int k = 0; k < EPT; ++k) d[k] = dur32[b * T_IN + j0 + k];
        } else {
#pragma unroll
            for (int k = 0; k < EPT; ++k) d[k] = dur32[(b * T_IN + j0 + k) * 2];
        }
    }
    int tot = 0;
    int pre[EPT];
#pragma unroll
    for (int k = 0; k < EPT; ++k) { pre[k] = tot; tot += d[k]; }

    const int lane = tid & 31;
    const int warp = tid >> 5;

    int incl = tot;
#pragma unroll
    for (int o = 1; o < 32; o <<= 1) {
        int n = __shfl_up_sync(0xffffffffu, incl, o);
        if (lane >= o) incl += n;
    }
    if (lane == 31) wsum[warp] = incl;
    __syncthreads();

    // all 32 lanes of warp 0 participate (partial-warp full-mask shfl hangs)
    if (warp == 0) {
        int w = (lane < NW) ? wsum[lane] : 0;
#pragma unroll
        for (int o = 1; o < 32; o <<= 1) {
            int n = __shfl_up_sync(0xffffffffu, w, o);
            if (lane >= o) w += n;
        }
        if (lane < NW) wsum[lane] = w;
    }
    __syncthreads();

    int base = (incl - tot) + (warp ? wsum[warp - 1] : 0);

    {
        const int j0 = tid * EPT;
#pragma unroll
        for (int k = 0; k < EPT; ++k) {
            const int s = base + pre[k];
            const int e = s + d[k];
            for (int t = s; t < e; ++t) sidx[t] = j0 + k;
        }
    }
    __syncthreads();

    // ---- Phase B: 2 channels x 2 t-groups, 16 LDGs in flight ----
    const int c0 = cg * CPB;
    const size_t rowbase = (size_t)(b * NC + c0);
    const int4* __restrict__ si4 = (const int4*)sidx;

#pragma unroll
    for (int cp = 0; cp < CPB; cp += 2) {
        const float* __restrict__ erow0 = enc + (rowbase + cp) * T_IN;
        const float* __restrict__ erow1 = erow0 + T_IN;
        float4* __restrict__ orow0 = (float4*)(out + (rowbase + cp) * T_OUT);
        float4* __restrict__ orow1 = orow0 + T_OUT / 4;

#pragma unroll
        for (int it = 0; it < (T_OUT / 4) / (2 * NT); ++it) {   // 2 steps
            const int ta = (2 * it) * NT + tid;
            const int tb = ta + NT;
            const int4 ia = si4[ta];
            const int4 ib = si4[tb];

            float4 a0, a1, b0, b1;          // 16 independent loads in flight
            a0.x = __ldg(erow0 + ia.x);
            a0.y = __ldg(erow0 + ia.y);
            a0.z = __ldg(erow0 + ia.z);
            a0.w = __ldg(erow0 + ia.w);
            a1.x = __ldg(erow1 + ia.x);
            a1.y = __ldg(erow1 + ia.y);
            a1.z = __ldg(erow1 + ia.z);
            a1.w = __ldg(erow1 + ia.w);
            b0.x = __ldg(erow0 + ib.x);
            b0.y = __ldg(erow0 + ib.y);
            b0.z = __ldg(erow0 + ib.z);
            b0.w = __ldg(erow0 + ib.w);
            b1.x = __ldg(erow1 + ib.x);
            b1.y = __ldg(erow1 + ib.y);
            b1.z = __ldg(erow1 + ib.z);
            b1.w = __ldg(erow1 + ib.w);

            __stcs(orow0 + ta, a0);
            __stcs(orow1 + ta, a1);
            __stcs(orow0 + tb, b0);
            __stcs(orow1 + tb, b1);
        }
    }
}

// ---------------------------------------------------------------------------
extern "C" void kernel_launch(void* const* d_in, const int* in_sizes, int n_in,
                              void* d_out, int out_size) {
    const void* enc_p = d_in[0];
    const void* dur_p = d_in[1];
    if (n_in >= 2 && in_sizes[0] == NB * T_IN) {    // durations came first
        dur_p = d_in[0];
        enc_p = d_in[1];
    }
    length_regulate_kernel<<<NB * (NC / CPB), NT>>>(
        (const float*)enc_p, (const int*)dur_p, (float*)d_out);
}

// round 17
// speedup vs baseline: 1.0639x; 1.0639x over previous
#include <cuda_runtime.h>
#include <stdint.h>

#define NB 32
#define NC 512
#define T_IN 1024
#define T_OUT 4096

#define CPB 8                    // channels per CTA -> grid = 2048
#define NT  256                  // threads per CTA
#define EPT (T_IN / NT)          // durations per thread in the scan = 4
#define NW  (NT / 32)            // warps per CTA = 8

// ---------------------------------------------------------------------------
// Fused kernel, smem-gather version. CTA = (batch, 8 channels).
//   Phase A : scan durations, scatter run-length index map to smem (u16, 8KB).
//   Phase A2: stage the CTA's 8 enc rows (contiguous 32KB in gmem) into smem
//             with one fully-coalesced float4 copy.
//   Phase B : gather via LDS (lane-consecutive indices -> ~conflict-free) and
//             stream STG.128 out. Scattered gather LDGs are GONE from L1tex,
//             leaving it to the write stream (R16 analysis: gather-LDG
//             wavefront replays were throttling store drain at ~57% DRAM).
// Index vector loaded once per t-group, reused across all 8 channels.
// Durations int32-vs-int64 detected on-device (odd words all zero => int64).
// ---------------------------------------------------------------------------
__global__ __launch_bounds__(NT, 5)
void length_regulate_kernel(const float* __restrict__ enc,
                            const int*   __restrict__ dur32,
                            float*       __restrict__ out) {
    const int groups_per_b = NC / CPB;              // 64
    const int b  = blockIdx.x / groups_per_b;
    const int cg = blockIdx.x % groups_per_b;
    const int tid = threadIdx.x;

    __shared__ unsigned short sidx[T_OUT];                  // 8 KB index map
    __shared__ __align__(16) float senc[CPB * T_IN];        // 32 KB enc rows
    __shared__ int wsum[NW];

    // ---- dtype detection: OR of odd words in first 2048 int32s ----
    int odd = 0;
#pragma unroll
    for (int i = 0; i < T_IN / NT; ++i)
        odd |= dur32[2 * (i * NT + tid) + 1];
    const bool is32 = __syncthreads_or(odd) != 0;

    // ---- Phase A2 (issue early): coalesced stage of 8 contiguous enc rows ----
    const int c0 = cg * CPB;
    const size_t rowbase = (size_t)(b * NC + c0);
    {
        const float4* __restrict__ g4 = (const float4*)(enc + rowbase * T_IN);
        float4* __restrict__ s4 = (float4*)senc;
#pragma unroll
        for (int i = 0; i < (CPB * T_IN / 4) / NT; ++i)     // 8 iters
            s4[i * NT + tid] = g4[i * NT + tid];
    }

    // ---- Phase A: scan + scatter (proven logic) ----
    int d[EPT];
    {
        const int j0 = tid * EPT;
        if (is32) {
#pragma unroll
            for (int k = 0; k < EPT; ++k) d[k] = dur32[b * T_IN + j0 + k];
        } else {
#pragma unroll
            for (int k = 0; k < EPT; ++k) d[k] = dur32[(b * T_IN + j0 + k) * 2];
        }
    }
    int tot = 0;
    int pre[EPT];
#pragma unroll
    for (int k = 0; k < EPT; ++k) { pre[k] = tot; tot += d[k]; }

    const int lane = tid & 31;
    const int warp = tid >> 5;

    int incl = tot;
#pragma unroll
    for (int o = 1; o < 32; o <<= 1) {
        int n = __shfl_up_sync(0xffffffffu, incl, o);
        if (lane >= o) incl += n;
    }
    if (lane == 31) wsum[warp] = incl;
    __syncthreads();

    // all 32 lanes of warp 0 participate (partial-warp full-mask shfl hangs)
    if (warp == 0) {
        int w = (lane < NW) ? wsum[lane] : 0;
#pragma unroll
        for (int o = 1; o < 32; o <<= 1) {
            int n = __shfl_up_sync(0xffffffffu, w, o);
            if (lane >= o) w += n;
        }
        if (lane < NW) wsum[lane] = w;
    }
    __syncthreads();

    int base = (incl - tot) + (warp ? wsum[warp - 1] : 0);

    {
        const int j0 = tid * EPT;
#pragma unroll
        for (int k = 0; k < EPT; ++k) {
            const int s = base + pre[k];
            const int e = s + d[k];
            for (int t = s; t < e; ++t) sidx[t] = (unsigned short)(j0 + k);
        }
    }
    __syncthreads();   // covers both sidx scatter and senc staging

    // ---- Phase B: LDS gather, index reused across 8 channels ----
#pragma unroll
    for (int it = 0; it < (T_OUT / 4) / NT; ++it) {         // 4 t-groups
        const int t4 = it * NT + tid;
        const uint2 p = *(const uint2*)(sidx + 4 * t4);     // 4 u16 indices
        const int i0 = p.x & 0xFFFF;
        const int i1 = p.x >> 16;
        const int i2 = p.y & 0xFFFF;
        const int i3 = p.y >> 16;

#pragma unroll
        for (int cc = 0; cc < CPB; ++cc) {
            const float* __restrict__ s = senc + cc * T_IN;
            float4 o;
            o.x = s[i0];
            o.y = s[i1];
            o.z = s[i2];
            o.w = s[i3];
            __stcs((float4*)(out + (rowbase + cc) * T_OUT) + t4, o);
        }
    }
}

// ---------------------------------------------------------------------------
extern "C" void kernel_launch(void* const* d_in, const int* in_sizes, int n_in,
                              void* d_out, int out_size) {
    const void* enc_p = d_in[0];
    const void* dur_p = d_in[1];
    if (n_in >= 2 && in_sizes[0] == NB * T_IN) {    // durations came first
        dur_p = d_in[0];
        enc_p = d_in[1];
    }
    length_regulate_kernel<<<NB * (NC / CPB), NT>>>(
        (const float*)enc_p, (const int*)dur_p, (float*)d_out);
}